// round 1
// baseline (speedup 1.0000x reference)
#include <cuda_runtime.h>
#include <cstdint>

// Problem constants (from reference_code)
#define BATCH   16384
#define NCONDS  50
#define EMB_DIM 64
#define IN_ROW  (1 + NCONDS)            // 51 int32 per batch row
#define OUT_ROW ((1 + NCONDS) * EMB_DIM) // 3264 floats per batch row

// One warp per batch row; each lane owns 2 embedding dims (float2).
__global__ void __launch_bounds__(256)
cond_filter_kernel(const int* __restrict__ inp,
                   const float* __restrict__ table,
                   float* __restrict__ out)
{
    const int warp = (blockIdx.x * blockDim.x + threadIdx.x) >> 5;
    const int lane = threadIdx.x & 31;
    if (warp >= BATCH) return;

    const int* __restrict__ row = inp + (size_t)warp * IN_ROW;
    float* __restrict__ orow = out + (size_t)warp * OUT_ROW;

    // ---- Event embedding: load, write raw, normalize in registers ----
    const int eidx = __ldg(row);  // uniform across warp -> broadcast
    const float2 ev = *reinterpret_cast<const float2*>(
        table + (size_t)eidx * EMB_DIM + lane * 2);

    // Raw (unnormalized) event embedding goes to output first 64 floats
    *reinterpret_cast<float2*>(orow + lane * 2) = ev;

    float ss = ev.x * ev.x + ev.y * ev.y;
    #pragma unroll
    for (int o = 16; o; o >>= 1)
        ss += __shfl_xor_sync(0xffffffffu, ss, o);
    const float einv = rsqrtf(ss);
    const float enx = ev.x * einv;
    const float eny = ev.y * einv;

    // ---- Conditions: gather, dual-reduce (sumsq + dot), fused scale ----
    float* __restrict__ crow = orow + EMB_DIM;
    #pragma unroll 2
    for (int c = 0; c < NCONDS; c++) {
        const int cidx = __ldg(row + 1 + c);  // uniform -> broadcast
        const float2 cv = *reinterpret_cast<const float2*>(
            table + (size_t)cidx * EMB_DIM + lane * 2);

        float s2 = cv.x * cv.x + cv.y * cv.y;   // ||cond||^2 partial
        float dt = cv.x * enx + cv.y * eny;     // <event_nrm, cond> partial
        #pragma unroll
        for (int o = 16; o; o >>= 1) {
            s2 += __shfl_xor_sync(0xffffffffu, s2, o);
            dt += __shfl_xor_sync(0xffffffffu, dt, o);
        }
        const float cinv  = rsqrtf(s2);
        // filtered = cond_nrm * score = cv * cinv * (dt * cinv) = cv * dt * cinv^2
        const float scale = dt * cinv * cinv;

        *reinterpret_cast<float2*>(crow + (size_t)c * EMB_DIM + lane * 2) =
            make_float2(cv.x * scale, cv.y * scale);
    }
}

extern "C" void kernel_launch(void* const* d_in, const int* in_sizes, int n_in,
                              void* d_out, int out_size)
{
    const int*   inp   = (const int*)d_in[0];     // (16384, 51) int32
    const float* table = (const float*)d_in[1];   // (100002, 64) float32
    float*       out   = (float*)d_out;           // (16384, 3264) float32

    const int threads = 256;                 // 8 warps/block
    const int total_threads = BATCH * 32;    // one warp per row
    const int blocks = (total_threads + threads - 1) / threads;
    cond_filter_kernel<<<blocks, threads>>>(inp, table, out);
}

// round 2
// speedup vs baseline: 1.2134x; 1.2134x over previous
#include <cuda_runtime.h>
#include <cstdint>

#define BATCH   16384
#define NCONDS  50
#define EMB_DIM 64
#define IN_ROW  (1 + NCONDS)             // 51 int32 per batch row
#define OUT_ROW ((1 + NCONDS) * EMB_DIM) // 3264 floats per batch row

// One warp per batch row. Each HALF-WARP (16 lanes x float4) owns one
// condition row at a time -> 2 conditions in flight per warp, 4-step
// butterfly reductions confined to the half-warp.
__global__ void __launch_bounds__(256)
cond_filter_kernel(const int* __restrict__ inp,
                   const float* __restrict__ table,
                   float* __restrict__ out)
{
    const int warp = (blockIdx.x * blockDim.x + threadIdx.x) >> 5;
    const int lane = threadIdx.x & 31;
    if (warp >= BATCH) return;

    const int hl   = lane & 15;   // lane within half-warp
    const int half = lane >> 4;   // which half-warp (0/1)

    const int* __restrict__ row  = inp + (size_t)warp * IN_ROW;
    float* __restrict__     orow = out + (size_t)warp * OUT_ROW;

    // ---- Event embedding: both halves load the same row as float4 ----
    const int eidx = __ldg(row);
    const float4 ev = *reinterpret_cast<const float4*>(
        table + (size_t)eidx * EMB_DIM + hl * 4);

    // Raw event embedding -> first 64 output floats (one half writes)
    if (half == 0)
        *reinterpret_cast<float4*>(orow + hl * 4) = ev;

    float ss = ev.x * ev.x + ev.y * ev.y + ev.z * ev.z + ev.w * ev.w;
    #pragma unroll
    for (int o = 8; o; o >>= 1)
        ss += __shfl_xor_sync(0xffffffffu, ss, o);   // stays within half
    const float einv = rsqrtf(ss);
    const float4 en = make_float4(ev.x * einv, ev.y * einv,
                                  ev.z * einv, ev.w * einv);

    // ---- Conditions: 2 per warp iteration (one per half-warp) ----
    float* __restrict__ crow = orow + EMB_DIM;
    #pragma unroll 5
    for (int c = 0; c < NCONDS; c += 2) {
        const int cidx = __ldg(row + 1 + c + half);
        const float4 cv = *reinterpret_cast<const float4*>(
            table + (size_t)cidx * EMB_DIM + hl * 4);

        float s2 = cv.x * cv.x + cv.y * cv.y + cv.z * cv.z + cv.w * cv.w;
        float dt = cv.x * en.x + cv.y * en.y + cv.z * en.z + cv.w * en.w;
        #pragma unroll
        for (int o = 8; o; o >>= 1) {
            s2 += __shfl_xor_sync(0xffffffffu, s2, o);
            dt += __shfl_xor_sync(0xffffffffu, dt, o);
        }
        const float cinv = rsqrtf(s2);
        // filtered = cond_nrm * score = cv * (dt * cinv^2)
        const float scale = dt * cinv * cinv;

        *reinterpret_cast<float4*>(crow + (size_t)(c + half) * EMB_DIM + hl * 4) =
            make_float4(cv.x * scale, cv.y * scale, cv.z * scale, cv.w * scale);
    }
}

extern "C" void kernel_launch(void* const* d_in, const int* in_sizes, int n_in,
                              void* d_out, int out_size)
{
    const int*   inp   = (const int*)d_in[0];     // (16384, 51) int32
    const float* table = (const float*)d_in[1];   // (100002, 64) float32
    float*       out   = (float*)d_out;           // (16384, 3264) float32

    const int threads = 256;                 // 8 warps/block
    const int total_threads = BATCH * 32;    // one warp per row
    const int blocks = (total_threads + threads - 1) / threads;
    cond_filter_kernel<<<blocks, threads>>>(inp, table, out);
}